// round 15
// baseline (speedup 1.0000x reference)
#include <cuda_runtime.h>
#include <cstdint>
#include <cstddef>

// B=4, H=8, N=256, D=32
//   scores[b,h,i,j,d] = q[b,h,i,d]*k[b,h,j,d]*edges[b,h,i,j,d]
//   logits = sum_d(scores)/sqrt(D) + mask[b,i,j]; attn = softmax_j
//   out[b,i,h*D+d]        = sum_j attn*v[b,h,j,d]
//   edge_out[b,j,i,h*D+d] = scores
// d_out = [ out (262144) | edge_out (67108864) ]
//
// v14 = v13 (CTA = one i-row x 8 heads, warp = head, monolithic softmax,
// 3 CTAs/SM for 444 resident slots -> 1024 tasks = 2.31 rounds = 1.5
// pair-units makespan vs v8's 2.0) with DEPTH 3->4: 64KB smem ring,
// lookahead 6KB/warp x 24 warps = 144KB outstanding per SM (> v8's 128KB
// which delivered 72% DRAM). Per-warp 2KB cp.async.bulk, count=8 mbarrier,
// no mainloop CTA barriers, online no-max softmax.

#define FULLM 0xffffffffu
#define JC        16                       // j per chunk
#define DEPTH     4
#define NCHUNK    16                       // 256 / JC
#define SLOT_FLOATS (8 * JC * 32)          // 4096 floats = 16KB
#define SECT_FLOATS (JC * 32)              // per-warp section: 512 floats = 2KB

__device__ __forceinline__ uint32_t s2u(const void* p) {
    uint32_t a;
    asm("{ .reg .u64 t; cvta.to.shared.u64 t, %1; cvt.u32.u64 %0, t; }"
        : "=r"(a) : "l"(p));
    return a;
}
__device__ __forceinline__ void mbar_init(uint32_t a, uint32_t cnt) {
    asm volatile("mbarrier.init.shared.b64 [%0], %1;" :: "r"(a), "r"(cnt) : "memory");
}
__device__ __forceinline__ void mbar_expect_tx(uint32_t a, uint32_t bytes) {
    asm volatile("mbarrier.arrive.expect_tx.shared.b64 _, [%0], %1;"
                 :: "r"(a), "r"(bytes) : "memory");
}
__device__ __forceinline__ void bulk_g2s(uint32_t dst, const void* src,
                                         uint32_t bytes, uint32_t mbar) {
    asm volatile(
        "cp.async.bulk.shared::cta.global.mbarrier::complete_tx::bytes "
        "[%0], [%1], %2, [%3];"
        :: "r"(dst), "l"(src), "r"(bytes), "r"(mbar) : "memory");
}
__device__ __forceinline__ void mbar_wait(uint32_t a, uint32_t parity) {
    asm volatile(
        "{\n\t.reg .pred P;\n\t"
        "WL_%=:\n\t"
        "mbarrier.try_wait.parity.shared.b64 P, [%0], %1, 0x989680;\n\t"
        "@P bra.uni WD_%=;\n\t"
        "bra.uni WL_%=;\n\t"
        "WD_%=:\n\t}"
        :: "r"(a), "r"(parity) : "memory");
}

__global__ __launch_bounds__(256, 3)
void edge_attn_v14(const float* __restrict__ q,
                   const float* __restrict__ k,
                   const float* __restrict__ v,
                   const float* __restrict__ e,
                   const float* __restrict__ mask,
                   float* __restrict__ out,
                   float* __restrict__ eout)
{
    extern __shared__ float dsm[];           // DEPTH * 16KB = 64KB
    __shared__ uint64_t mbar[DEPTH];

    const int tid  = threadIdx.x;
    const int w    = tid >> 5;     // warp = head h
    const int lane = tid & 31;
    const int o    = lane >> 3;    // octet: j within 4-group
    const int cc   = lane & 7;     // d-chunk (4 floats)

    const int cta = blockIdx.x;    // 0..1023
    const int b   = cta >> 8;
    const int i   = cta & 255;
    const int bh  = b * 8 + w;

    const float4 qv = *(const float4*)(q + ((size_t)bh * 256 + i) * 32 + cc * 4);
    const float4* __restrict__ kb4 = (const float4*)(k + (size_t)bh * 8192) + cc;
    const float4* __restrict__ vb4 = (const float4*)(v + (size_t)bh * 8192) + cc;
    const float*  __restrict__ mr  = mask + ((size_t)b * 256 + i) * 256;
    const float*  __restrict__ es  = e + ((size_t)bh * 256 + i) * 8192;
    // edge_out float4 index for j=0: b*4194304 + j*16384 + i*64 + h*8 + cc
    float4* __restrict__ eo = (float4*)eout
        + (size_t)b * 4194304 + (size_t)i * 64 + w * 8 + cc;

    uint32_t mb[DEPTH];
    #pragma unroll
    for (int s = 0; s < DEPTH; ++s) mb[s] = s2u(&mbar[s]);
    const uint32_t dsm_u = s2u(dsm);
    const uint32_t sect0 = dsm_u + (uint32_t)(w * SECT_FLOATS) * 4;

    if (tid == 0) {
        #pragma unroll
        for (int s = 0; s < DEPTH; ++s) mbar_init(mb[s], 8);
        asm volatile("fence.proxy.async.shared::cta;" ::: "memory");
    }
    __syncthreads();   // the ONLY CTA barrier

    // per-warp prologue: chunks 0..DEPTH-1 (one 2KB copy each)
    if (lane == 0) {
        #pragma unroll
        for (int s = 0; s < DEPTH; ++s) {
            const uint32_t base = sect0 + (uint32_t)(s * SLOT_FLOATS) * 4;
            mbar_expect_tx(mb[s], SECT_FLOATS * 4);
            bulk_g2s(base, es + s * SECT_FLOATS, SECT_FLOATS * 4, mb[s]);
        }
    }

    const float SCALE = 0.17677669529663687f;  // 1/sqrt(32)

    float4 acc = make_float4(0.f, 0.f, 0.f, 0.f);
    float  ssum = 0.f;

    int slot = 0, parity = 0;
    for (int c = 0; c < NCHUNK; ++c) {
        mbar_wait(mb[slot], parity);

        const float* __restrict__ buf = dsm + slot * SLOT_FLOATS + w * SECT_FLOATS;

        #pragma unroll
        for (int g = 0; g < 4; ++g) {
            const int jl = g * 4 + o;       // 0..15
            const int j  = c * JC + jl;
            float4 k4 = __ldg(kb4 + (size_t)j * 8);
            float4 v4 = __ldg(vb4 + (size_t)j * 8);
            float4 e4 = *(const float4*)(buf + jl * 32 + cc * 4);

            float4 s;
            s.x = qv.x * k4.x * e4.x;
            s.y = qv.y * k4.y * e4.y;
            s.z = qv.z * k4.z * e4.z;
            s.w = qv.w * k4.w * e4.w;
            eo[(size_t)j * 16384] = s;      // .wb store; concurrent CTAs tile the plane

            float t = (s.x + s.y) + (s.z + s.w);
            t += __shfl_xor_sync(FULLM, t, 1);
            t += __shfl_xor_sync(FULLM, t, 2);
            t += __shfl_xor_sync(FULLM, t, 4);

            float p = __expf(t * SCALE + __ldg(mr + j));  // no-max softmax
            ssum += p;
            acc.x = fmaf(p, v4.x, acc.x);
            acc.y = fmaf(p, v4.y, acc.y);
            acc.z = fmaf(p, v4.z, acc.z);
            acc.w = fmaf(p, v4.w, acc.w);
        }

        __syncwarp();   // warp done reading its section
        if (lane == 0 && c + DEPTH < NCHUNK) {
            const int nc = c + DEPTH;
            const uint32_t base = sect0 + (uint32_t)(slot * SLOT_FLOATS) * 4;
            mbar_expect_tx(mb[slot], SECT_FLOATS * 4);
            bulk_g2s(base, es + nc * SECT_FLOATS, SECT_FLOATS * 4, mb[slot]);
        }
        if (++slot == DEPTH) { slot = 0; parity ^= 1; }
    }

    // warp-local epilogue: combine the 4 octets (j mod 4 partitions)
    #pragma unroll
    for (int off = 8; off <= 16; off <<= 1) {
        acc.x += __shfl_xor_sync(FULLM, acc.x, off);
        acc.y += __shfl_xor_sync(FULLM, acc.y, off);
        acc.z += __shfl_xor_sync(FULLM, acc.z, off);
        acc.w += __shfl_xor_sync(FULLM, acc.w, off);
        ssum  += __shfl_xor_sync(FULLM, ssum,  off);
    }
    if (o == 0) {
        const float r = 1.0f / ssum;
        float4 ov = make_float4(acc.x * r, acc.y * r, acc.z * r, acc.w * r);
        *(float4*)(out + ((size_t)b * 256 + i) * 256 + w * 32 + cc * 4) = ov;
    }
}

extern "C" void kernel_launch(void* const* d_in, const int* in_sizes, int n_in,
                              void* d_out, int out_size)
{
    const float* q    = (const float*)d_in[0];
    const float* k    = (const float*)d_in[1];
    const float* v    = (const float*)d_in[2];
    const float* e    = (const float*)d_in[3];
    const float* mask = (const float*)d_in[4];
    float* out  = (float*)d_out;
    float* eout = out + (size_t)4 * 256 * 256;  // 262144

    const int dyn_smem = DEPTH * SLOT_FLOATS * 4;   // 64KB
    cudaFuncSetAttribute(edge_attn_v14,
                         cudaFuncAttributeMaxDynamicSharedMemorySize, dyn_smem);
    edge_attn_v14<<<1024, 256, dyn_smem>>>(q, k, v, e, mask, out, eout);
}

// round 16
// speedup vs baseline: 1.1405x; 1.1405x over previous
#include <cuda_runtime.h>
#include <cstdint>
#include <cstddef>

// B=4, H=8, N=256, D=32
//   scores[b,h,i,j,d] = q[b,h,i,d]*k[b,h,j,d]*edges[b,h,i,j,d]
//   logits = sum_d(scores)/sqrt(D) + mask[b,i,j]; attn = softmax_j
//   out[b,i,h*D+d]        = sum_j attn*v[b,h,j,d]
//   edge_out[b,j,i,h*D+d] = scores
// d_out = [ out (262144) | edge_out (67108864) ]
//
// v15 = v8 EXACTLY (measured best: 94.1us wall, 72.2% DRAM) + L2
// evict_first cache hint on the edges bulk-copy reads. edges are
// touch-once; keeping their lines out of L2 leaves the full 126MB for
// dirty edge_out lines -> larger write-back bursts -> better DRAM row
// locality on the 256MB write stream (the .wb-vs-.cs experiment in R4
// proved write aggregation is worth real bandwidth).

#define FULLM 0xffffffffu
#define JC        16                       // j per chunk
#define DEPTH     3
#define NCHUNK    16                       // 256 / JC
#define SLOT_FLOATS (8 * 2 * JC * 32)      // 8192 floats = 32KB
#define SECT_FLOATS (2 * JC * 32)          // per-warp section: 1024
#define HALF_FLOATS (JC * 32)              // per (h,i): 512 floats = 2KB

__device__ __forceinline__ uint32_t s2u(const void* p) {
    uint32_t a;
    asm("{ .reg .u64 t; cvta.to.shared.u64 t, %1; cvt.u32.u64 %0, t; }"
        : "=r"(a) : "l"(p));
    return a;
}
__device__ __forceinline__ void mbar_init(uint32_t a, uint32_t cnt) {
    asm volatile("mbarrier.init.shared.b64 [%0], %1;" :: "r"(a), "r"(cnt) : "memory");
}
__device__ __forceinline__ void mbar_expect_tx(uint32_t a, uint32_t bytes) {
    asm volatile("mbarrier.arrive.expect_tx.shared.b64 _, [%0], %1;"
                 :: "r"(a), "r"(bytes) : "memory");
}
__device__ __forceinline__ uint64_t mk_evict_first_policy() {
    uint64_t pol;
    asm("createpolicy.fractional.L2::evict_first.b64 %0;" : "=l"(pol));
    return pol;
}
// bulk copy with L2 evict_first cache hint (read-once stream)
__device__ __forceinline__ void bulk_g2s_ef(uint32_t dst, const void* src,
                                            uint32_t bytes, uint32_t mbar,
                                            uint64_t pol) {
    asm volatile(
        "cp.async.bulk.shared::cta.global.mbarrier::complete_tx::bytes.L2::cache_hint "
        "[%0], [%1], %2, [%3], %4;"
        :: "r"(dst), "l"(src), "r"(bytes), "r"(mbar), "l"(pol) : "memory");
}
__device__ __forceinline__ void mbar_wait(uint32_t a, uint32_t parity) {
    asm volatile(
        "{\n\t.reg .pred P;\n\t"
        "WL_%=:\n\t"
        "mbarrier.try_wait.parity.shared.b64 P, [%0], %1, 0x989680;\n\t"
        "@P bra.uni WD_%=;\n\t"
        "bra.uni WL_%=;\n\t"
        "WD_%=:\n\t}"
        :: "r"(a), "r"(parity) : "memory");
}

__global__ __launch_bounds__(256, 2)
void edge_attn_v15(const float* __restrict__ q,
                   const float* __restrict__ k,
                   const float* __restrict__ v,
                   const float* __restrict__ e,
                   const float* __restrict__ mask,
                   float* __restrict__ out,
                   float* __restrict__ eout)
{
    extern __shared__ float dsm[];           // DEPTH * 32KB = 96KB
    __shared__ uint64_t mbar[DEPTH];

    const int tid  = threadIdx.x;
    const int w    = tid >> 5;     // warp = head h
    const int lane = tid & 31;
    const int o    = lane >> 3;    // octet: j within 4-group
    const int cc   = lane & 7;     // d-chunk (4 floats)

    const int cta = blockIdx.x;    // 0..511
    const int b   = cta >> 7;
    const int i0  = (cta & 127) * 2;
    const int bh  = b * 8 + w;

    const float4 qv0 = *(const float4*)(q + ((size_t)bh * 256 + i0    ) * 32 + cc * 4);
    const float4 qv1 = *(const float4*)(q + ((size_t)bh * 256 + i0 + 1) * 32 + cc * 4);
    const float4* __restrict__ kb4 = (const float4*)(k + (size_t)bh * 8192) + cc;
    const float4* __restrict__ vb4 = (const float4*)(v + (size_t)bh * 8192) + cc;
    const float*  __restrict__ mr0 = mask + ((size_t)b * 256 + i0) * 256;
    const float*  __restrict__ mr1 = mr0 + 256;
    const float*  __restrict__ es0 = e + ((size_t)bh * 256 + i0) * 8192;
    const float*  __restrict__ es1 = es0 + 8192;
    // edge_out float4 index for j=0: b*4194304 + j*16384 + i*64 + h*8 + cc
    float4* __restrict__ eo0 = (float4*)eout
        + (size_t)b * 4194304 + (size_t)i0 * 64 + w * 8 + cc;
    float4* __restrict__ eo1 = eo0 + 64;     // i0+1

    uint32_t mb[DEPTH];
    #pragma unroll
    for (int s = 0; s < DEPTH; ++s) mb[s] = s2u(&mbar[s]);
    const uint32_t dsm_u = s2u(dsm);
    const uint32_t sect0 = dsm_u + (uint32_t)(w * SECT_FLOATS) * 4;
    const uint64_t pol = mk_evict_first_policy();

    if (tid == 0) {
        #pragma unroll
        for (int s = 0; s < DEPTH; ++s) mbar_init(mb[s], 8);
        asm volatile("fence.proxy.async.shared::cta;" ::: "memory");
    }
    __syncthreads();   // the ONLY CTA barrier

    // per-warp prologue: chunks 0..2
    if (lane == 0) {
        #pragma unroll
        for (int s = 0; s < DEPTH; ++s) {
            const uint32_t base = sect0 + (uint32_t)(s * SLOT_FLOATS) * 4;
            mbar_expect_tx(mb[s], 2 * HALF_FLOATS * 4);
            bulk_g2s_ef(base,                   es0 + s * HALF_FLOATS, HALF_FLOATS * 4, mb[s], pol);
            bulk_g2s_ef(base + HALF_FLOATS * 4, es1 + s * HALF_FLOATS, HALF_FLOATS * 4, mb[s], pol);
        }
    }

    const float SCALE = 0.17677669529663687f;  // 1/sqrt(32)

    float4 acc0 = make_float4(0.f, 0.f, 0.f, 0.f);
    float4 acc1 = make_float4(0.f, 0.f, 0.f, 0.f);
    float  ss0 = 0.f, ss1 = 0.f;

    int slot = 0, parity = 0;
    for (int c = 0; c < NCHUNK; ++c) {
        mbar_wait(mb[slot], parity);

        const float* __restrict__ buf0 = dsm + slot * SLOT_FLOATS + w * SECT_FLOATS;
        const float* __restrict__ buf1 = buf0 + HALF_FLOATS;

        #pragma unroll
        for (int g = 0; g < 4; ++g) {
            const int jl = g * 4 + o;       // 0..15
            const int j  = c * JC + jl;
            float4 k4 = __ldg(kb4 + (size_t)j * 8);
            float4 v4 = __ldg(vb4 + (size_t)j * 8);
            float4 e0 = *(const float4*)(buf0 + jl * 32 + cc * 4);
            float4 e1 = *(const float4*)(buf1 + jl * 32 + cc * 4);

            float4 s0, s1;
            s0.x = qv0.x * k4.x * e0.x;  s1.x = qv1.x * k4.x * e1.x;
            s0.y = qv0.y * k4.y * e0.y;  s1.y = qv1.y * k4.y * e1.y;
            s0.z = qv0.z * k4.z * e0.z;  s1.z = qv1.z * k4.z * e1.z;
            s0.w = qv0.w * k4.w * e0.w;  s1.w = qv1.w * k4.w * e1.w;
            eo0[(size_t)j * 16384] = s0;
            eo1[(size_t)j * 16384] = s1;

            float t0 = (s0.x + s0.y) + (s0.z + s0.w);
            float t1 = (s1.x + s1.y) + (s1.z + s1.w);
            t0 += __shfl_xor_sync(FULLM, t0, 1);
            t1 += __shfl_xor_sync(FULLM, t1, 1);
            t0 += __shfl_xor_sync(FULLM, t0, 2);
            t1 += __shfl_xor_sync(FULLM, t1, 2);
            t0 += __shfl_xor_sync(FULLM, t0, 4);
            t1 += __shfl_xor_sync(FULLM, t1, 4);

            float p0 = __expf(t0 * SCALE + __ldg(mr0 + j));  // no-max softmax
            float p1 = __expf(t1 * SCALE + __ldg(mr1 + j));
            ss0 += p0;  ss1 += p1;
            acc0.x = fmaf(p0, v4.x, acc0.x);  acc1.x = fmaf(p1, v4.x, acc1.x);
            acc0.y = fmaf(p0, v4.y, acc0.y);  acc1.y = fmaf(p1, v4.y, acc1.y);
            acc0.z = fmaf(p0, v4.z, acc0.z);  acc1.z = fmaf(p1, v4.z, acc1.z);
            acc0.w = fmaf(p0, v4.w, acc0.w);  acc1.w = fmaf(p1, v4.w, acc1.w);
        }

        __syncwarp();   // warp done reading its section
        if (lane == 0 && c + DEPTH < NCHUNK) {
            const int nc = c + DEPTH;
            const uint32_t base = sect0 + (uint32_t)(slot * SLOT_FLOATS) * 4;
            mbar_expect_tx(mb[slot], 2 * HALF_FLOATS * 4);
            bulk_g2s_ef(base,                   es0 + nc * HALF_FLOATS, HALF_FLOATS * 4, mb[slot], pol);
            bulk_g2s_ef(base + HALF_FLOATS * 4, es1 + nc * HALF_FLOATS, HALF_FLOATS * 4, mb[slot], pol);
        }
        if (++slot == DEPTH) { slot = 0; parity ^= 1; }
    }

    // warp-local epilogue: combine the 4 octets (j mod 4 partitions)
    #pragma unroll
    for (int off = 8; off <= 16; off <<= 1) {
        acc0.x += __shfl_xor_sync(FULLM, acc0.x, off);
        acc0.y += __shfl_xor_sync(FULLM, acc0.y, off);
        acc0.z += __shfl_xor_sync(FULLM, acc0.z, off);
        acc0.w += __shfl_xor_sync(FULLM, acc0.w, off);
        ss0    += __shfl_xor_sync(FULLM, ss0,    off);
        acc1.x += __shfl_xor_sync(FULLM, acc1.x, off);
        acc1.y += __shfl_xor_sync(FULLM, acc1.y, off);
        acc1.z += __shfl_xor_sync(FULLM, acc1.z, off);
        acc1.w += __shfl_xor_sync(FULLM, acc1.w, off);
        ss1    += __shfl_xor_sync(FULLM, ss1,    off);
    }
    if (o == 0) {
        const float r0 = 1.0f / ss0, r1 = 1.0f / ss1;
        float4 o0 = make_float4(acc0.x * r0, acc0.y * r0, acc0.z * r0, acc0.w * r0);
        float4 o1 = make_float4(acc1.x * r1, acc1.y * r1, acc1.z * r1, acc1.w * r1);
        float* obase = out + ((size_t)b * 256 + i0) * 256 + w * 32 + cc * 4;
        *(float4*)obase         = o0;
        *(float4*)(obase + 256) = o1;
    }
}

extern "C" void kernel_launch(void* const* d_in, const int* in_sizes, int n_in,
                              void* d_out, int out_size)
{
    const float* q    = (const float*)d_in[0];
    const float* k    = (const float*)d_in[1];
    const float* v    = (const float*)d_in[2];
    const float* e    = (const float*)d_in[3];
    const float* mask = (const float*)d_in[4];
    float* out  = (float*)d_out;
    float* eout = out + (size_t)4 * 256 * 256;  // 262144

    const int dyn_smem = DEPTH * SLOT_FLOATS * 4;   // 96KB
    cudaFuncSetAttribute(edge_attn_v15,
                         cudaFuncAttributeMaxDynamicSharedMemorySize, dyn_smem);
    edge_attn_v15<<<512, 256, dyn_smem>>>(q, k, v, e, mask, out, eout);
}

// round 17
// speedup vs baseline: 1.1991x; 1.0513x over previous
#include <cuda_runtime.h>
#include <cstdint>
#include <cstddef>

// B=4, H=8, N=256, D=32
//   scores[b,h,i,j,d] = q[b,h,i,d]*k[b,h,j,d]*edges[b,h,i,j,d]
//   logits = sum_d(scores)/sqrt(D) + mask[b,i,j]; attn = softmax_j
//   out[b,i,h*D+d]        = sum_j attn*v[b,h,j,d]
//   edge_out[b,j,i,h*D+d] = scores
// d_out = [ out (262144) | edge_out (67108864) ]
//
// v16 = v8 EXACTLY (measured best: 94.1us wall, 72.2% DRAM) + L2
// evict_last cache hint on the edge_out STORES only. Dirty lines persist
// in L2 until the temporally-clustered neighbor CTAs complete each 2KB/j
// neighborhood -> larger contiguous write-back bursts (write aggregation
// is the proven lever: R4 +8% DRAM, R7/R8 +10%). Reads keep the default
// policy (R15 showed read-side hints are negative).

#define FULLM 0xffffffffu
#define JC        16                       // j per chunk
#define DEPTH     3
#define NCHUNK    16                       // 256 / JC
#define SLOT_FLOATS (8 * 2 * JC * 32)      // 8192 floats = 32KB
#define SECT_FLOATS (2 * JC * 32)          // per-warp section: 1024
#define HALF_FLOATS (JC * 32)              // per (h,i): 512 floats = 2KB

__device__ __forceinline__ uint32_t s2u(const void* p) {
    uint32_t a;
    asm("{ .reg .u64 t; cvta.to.shared.u64 t, %1; cvt.u32.u64 %0, t; }"
        : "=r"(a) : "l"(p));
    return a;
}
__device__ __forceinline__ void mbar_init(uint32_t a, uint32_t cnt) {
    asm volatile("mbarrier.init.shared.b64 [%0], %1;" :: "r"(a), "r"(cnt) : "memory");
}
__device__ __forceinline__ void mbar_expect_tx(uint32_t a, uint32_t bytes) {
    asm volatile("mbarrier.arrive.expect_tx.shared.b64 _, [%0], %1;"
                 :: "r"(a), "r"(bytes) : "memory");
}
__device__ __forceinline__ void bulk_g2s(uint32_t dst, const void* src,
                                         uint32_t bytes, uint32_t mbar) {
    asm volatile(
        "cp.async.bulk.shared::cta.global.mbarrier::complete_tx::bytes "
        "[%0], [%1], %2, [%3];"
        :: "r"(dst), "l"(src), "r"(bytes), "r"(mbar) : "memory");
}
__device__ __forceinline__ void mbar_wait(uint32_t a, uint32_t parity) {
    asm volatile(
        "{\n\t.reg .pred P;\n\t"
        "WL_%=:\n\t"
        "mbarrier.try_wait.parity.shared.b64 P, [%0], %1, 0x989680;\n\t"
        "@P bra.uni WD_%=;\n\t"
        "bra.uni WL_%=;\n\t"
        "WD_%=:\n\t}"
        :: "r"(a), "r"(parity) : "memory");
}
__device__ __forceinline__ uint64_t mk_evict_last_policy() {
    uint64_t pol;
    asm("createpolicy.fractional.L2::evict_last.b64 %0;" : "=l"(pol));
    return pol;
}
// 128-bit store with L2 evict_last cache hint
__device__ __forceinline__ void stg128_el(float4* addr, float4 s, uint64_t pol) {
    asm volatile(
        "st.global.L2::cache_hint.v4.f32 [%0], {%1, %2, %3, %4}, %5;"
        :: "l"(addr), "f"(s.x), "f"(s.y), "f"(s.z), "f"(s.w), "l"(pol)
        : "memory");
}

__global__ __launch_bounds__(256, 2)
void edge_attn_v16(const float* __restrict__ q,
                   const float* __restrict__ k,
                   const float* __restrict__ v,
                   const float* __restrict__ e,
                   const float* __restrict__ mask,
                   float* __restrict__ out,
                   float* __restrict__ eout)
{
    extern __shared__ float dsm[];           // DEPTH * 32KB = 96KB
    __shared__ uint64_t mbar[DEPTH];

    const int tid  = threadIdx.x;
    const int w    = tid >> 5;     // warp = head h
    const int lane = tid & 31;
    const int o    = lane >> 3;    // octet: j within 4-group
    const int cc   = lane & 7;     // d-chunk (4 floats)

    const int cta = blockIdx.x;    // 0..511
    const int b   = cta >> 7;
    const int i0  = (cta & 127) * 2;
    const int bh  = b * 8 + w;

    const float4 qv0 = *(const float4*)(q + ((size_t)bh * 256 + i0    ) * 32 + cc * 4);
    const float4 qv1 = *(const float4*)(q + ((size_t)bh * 256 + i0 + 1) * 32 + cc * 4);
    const float4* __restrict__ kb4 = (const float4*)(k + (size_t)bh * 8192) + cc;
    const float4* __restrict__ vb4 = (const float4*)(v + (size_t)bh * 8192) + cc;
    const float*  __restrict__ mr0 = mask + ((size_t)b * 256 + i0) * 256;
    const float*  __restrict__ mr1 = mr0 + 256;
    const float*  __restrict__ es0 = e + ((size_t)bh * 256 + i0) * 8192;
    const float*  __restrict__ es1 = es0 + 8192;
    // edge_out float4 index for j=0: b*4194304 + j*16384 + i*64 + h*8 + cc
    float4* __restrict__ eo0 = (float4*)eout
        + (size_t)b * 4194304 + (size_t)i0 * 64 + w * 8 + cc;
    float4* __restrict__ eo1 = eo0 + 64;     // i0+1

    uint32_t mb[DEPTH];
    #pragma unroll
    for (int s = 0; s < DEPTH; ++s) mb[s] = s2u(&mbar[s]);
    const uint32_t dsm_u = s2u(dsm);
    const uint32_t sect0 = dsm_u + (uint32_t)(w * SECT_FLOATS) * 4;
    const uint64_t pol = mk_evict_last_policy();

    if (tid == 0) {
        #pragma unroll
        for (int s = 0; s < DEPTH; ++s) mbar_init(mb[s], 8);
        asm volatile("fence.proxy.async.shared::cta;" ::: "memory");
    }
    __syncthreads();   // the ONLY CTA barrier

    // per-warp prologue: chunks 0..2
    if (lane == 0) {
        #pragma unroll
        for (int s = 0; s < DEPTH; ++s) {
            const uint32_t base = sect0 + (uint32_t)(s * SLOT_FLOATS) * 4;
            mbar_expect_tx(mb[s], 2 * HALF_FLOATS * 4);
            bulk_g2s(base,                   es0 + s * HALF_FLOATS, HALF_FLOATS * 4, mb[s]);
            bulk_g2s(base + HALF_FLOATS * 4, es1 + s * HALF_FLOATS, HALF_FLOATS * 4, mb[s]);
        }
    }

    const float SCALE = 0.17677669529663687f;  // 1/sqrt(32)

    float4 acc0 = make_float4(0.f, 0.f, 0.f, 0.f);
    float4 acc1 = make_float4(0.f, 0.f, 0.f, 0.f);
    float  ss0 = 0.f, ss1 = 0.f;

    int slot = 0, parity = 0;
    for (int c = 0; c < NCHUNK; ++c) {
        mbar_wait(mb[slot], parity);

        const float* __restrict__ buf0 = dsm + slot * SLOT_FLOATS + w * SECT_FLOATS;
        const float* __restrict__ buf1 = buf0 + HALF_FLOATS;

        #pragma unroll
        for (int g = 0; g < 4; ++g) {
            const int jl = g * 4 + o;       // 0..15
            const int j  = c * JC + jl;
            float4 k4 = __ldg(kb4 + (size_t)j * 8);
            float4 v4 = __ldg(vb4 + (size_t)j * 8);
            float4 e0 = *(const float4*)(buf0 + jl * 32 + cc * 4);
            float4 e1 = *(const float4*)(buf1 + jl * 32 + cc * 4);

            float4 s0, s1;
            s0.x = qv0.x * k4.x * e0.x;  s1.x = qv1.x * k4.x * e1.x;
            s0.y = qv0.y * k4.y * e0.y;  s1.y = qv1.y * k4.y * e1.y;
            s0.z = qv0.z * k4.z * e0.z;  s1.z = qv1.z * k4.z * e1.z;
            s0.w = qv0.w * k4.w * e0.w;  s1.w = qv1.w * k4.w * e1.w;
            stg128_el(eo0 + (size_t)j * 16384, s0, pol);
            stg128_el(eo1 + (size_t)j * 16384, s1, pol);

            float t0 = (s0.x + s0.y) + (s0.z + s0.w);
            float t1 = (s1.x + s1.y) + (s1.z + s1.w);
            t0 += __shfl_xor_sync(FULLM, t0, 1);
            t1 += __shfl_xor_sync(FULLM, t1, 1);
            t0 += __shfl_xor_sync(FULLM, t0, 2);
            t1 += __shfl_xor_sync(FULLM, t1, 2);
            t0 += __shfl_xor_sync(FULLM, t0, 4);
            t1 += __shfl_xor_sync(FULLM, t1, 4);

            float p0 = __expf(t0 * SCALE + __ldg(mr0 + j));  // no-max softmax
            float p1 = __expf(t1 * SCALE + __ldg(mr1 + j));
            ss0 += p0;  ss1 += p1;
            acc0.x = fmaf(p0, v4.x, acc0.x);  acc1.x = fmaf(p1, v4.x, acc1.x);
            acc0.y = fmaf(p0, v4.y, acc0.y);  acc1.y = fmaf(p1, v4.y, acc1.y);
            acc0.z = fmaf(p0, v4.z, acc0.z);  acc1.z = fmaf(p1, v4.z, acc1.z);
            acc0.w = fmaf(p0, v4.w, acc0.w);  acc1.w = fmaf(p1, v4.w, acc1.w);
        }

        __syncwarp();   // warp done reading its section
        if (lane == 0 && c + DEPTH < NCHUNK) {
            const int nc = c + DEPTH;
            const uint32_t base = sect0 + (uint32_t)(slot * SLOT_FLOATS) * 4;
            mbar_expect_tx(mb[slot], 2 * HALF_FLOATS * 4);
            bulk_g2s(base,                   es0 + nc * HALF_FLOATS, HALF_FLOATS * 4, mb[slot]);
            bulk_g2s(base + HALF_FLOATS * 4, es1 + nc * HALF_FLOATS, HALF_FLOATS * 4, mb[slot]);
        }
        if (++slot == DEPTH) { slot = 0; parity ^= 1; }
    }

    // warp-local epilogue: combine the 4 octets (j mod 4 partitions)
    #pragma unroll
    for (int off = 8; off <= 16; off <<= 1) {
        acc0.x += __shfl_xor_sync(FULLM, acc0.x, off);
        acc0.y += __shfl_xor_sync(FULLM, acc0.y, off);
        acc0.z += __shfl_xor_sync(FULLM, acc0.z, off);
        acc0.w += __shfl_xor_sync(FULLM, acc0.w, off);
        ss0    += __shfl_xor_sync(FULLM, ss0,    off);
        acc1.x += __shfl_xor_sync(FULLM, acc1.x, off);
        acc1.y += __shfl_xor_sync(FULLM, acc1.y, off);
        acc1.z += __shfl_xor_sync(FULLM, acc1.z, off);
        acc1.w += __shfl_xor_sync(FULLM, acc1.w, off);
        ss1    += __shfl_xor_sync(FULLM, ss1,    off);
    }
    if (o == 0) {
        const float r0 = 1.0f / ss0, r1 = 1.0f / ss1;
        float4 o0 = make_float4(acc0.x * r0, acc0.y * r0, acc0.z * r0, acc0.w * r0);
        float4 o1 = make_float4(acc1.x * r1, acc1.y * r1, acc1.z * r1, acc1.w * r1);
        float* obase = out + ((size_t)b * 256 + i0) * 256 + w * 32 + cc * 4;
        *(float4*)obase         = o0;
        *(float4*)(obase + 256) = o1;
    }
}

extern "C" void kernel_launch(void* const* d_in, const int* in_sizes, int n_in,
                              void* d_out, int out_size)
{
    const float* q    = (const float*)d_in[0];
    const float* k    = (const float*)d_in[1];
    const float* v    = (const float*)d_in[2];
    const float* e    = (const float*)d_in[3];
    const float* mask = (const float*)d_in[4];
    float* out  = (float*)d_out;
    float* eout = out + (size_t)4 * 256 * 256;  // 262144

    const int dyn_smem = DEPTH * SLOT_FLOATS * 4;   // 96KB
    cudaFuncSetAttribute(edge_attn_v16,
                         cudaFuncAttributeMaxDynamicSharedMemorySize, dyn_smem);
    edge_attn_v16<<<512, 256, dyn_smem>>>(q, k, v, e, mask, out, eout);
}